// round 4
// baseline (speedup 1.0000x reference)
#include <cuda_runtime.h>
#include <cuda_bf16.h>
#include <mma.h>

using namespace nvcuda;

// ---------------- problem constants (fixed by setup_inputs) ----------------
#define B_   2
#define L_   2048
#define DM   1024
#define H_   16
#define DK   64
#define W2   512          // window_size / 2

// ---------------- device scratch (allocation-free) ----------------
__device__ float g_Q[(size_t)B_ * H_ * L_ * DK];   // [b][h][l][k]
__device__ float g_K[(size_t)B_ * H_ * L_ * DK];
__device__ float g_V[(size_t)B_ * H_ * L_ * DK];
__device__ float g_O[(size_t)B_ * L_ * DM];        // [(b*L+l)][h*64+d]
__device__ float g_Y[(size_t)B_ * L_ * DM];        // Wo output
__device__ float g_bias[L_];                       // exp(-|rel|/s/tau), rel=0..L-1

// ---------------- helpers ----------------
__device__ __forceinline__ void st4_tf32(float* d, float4 v) {
    d[0] = wmma::__float_to_tf32(v.x);
    d[1] = wmma::__float_to_tf32(v.y);
    d[2] = wmma::__float_to_tf32(v.z);
    d[3] = wmma::__float_to_tf32(v.w);
}

// ---------------- bias table ----------------
__global__ void bias_kernel(const float* __restrict__ sf, const float* __restrict__ tau) {
    int r = blockIdx.x * blockDim.x + threadIdx.x;
    if (r < L_) g_bias[r] = expf(-fabsf((float)r / sf[0]) / tau[0]);
}

// ---------------- tf32 GEMM: C[M,N] = A[M,1024] * B[N,1024]^T ----------------
// mode 0: blockIdx.z in {0,1,2} selects (A,B) from q/k/v + Wq/Wk/Wv, writes head-major g_Q/g_K/g_V
// mode 1: A = g_O, B = B0 (Wo), writes g_Y row-major
__global__ __launch_bounds__(256) void gemm_kernel(
    const float* __restrict__ A0, const float* __restrict__ A1, const float* __restrict__ A2,
    const float* __restrict__ B0, const float* __restrict__ B1, const float* __restrict__ B2,
    int mode)
{
    __shared__ float sA[64 * 36];
    __shared__ float sB[64 * 36];

    const int tid = threadIdx.x;
    const int w   = tid >> 5;
    const int wr  = w >> 2;     // 0..1  (32-row half)
    const int wc  = w & 3;      // 0..3  (16-col slice)
    const int z   = blockIdx.z;
    const int m0  = blockIdx.y * 64;
    const int n0  = blockIdx.x * 64;

    const float* A  = (mode == 1) ? A0 : (z == 0 ? A0 : (z == 1 ? A1 : A2));
    const float* Bw = (mode == 1) ? B0 : (z == 0 ? B0 : (z == 1 ? B1 : B2));
    if (mode == 1) A = g_O;

    wmma::fragment<wmma::accumulator, 16, 16, 8, float> acc0, acc1;
    wmma::fill_fragment(acc0, 0.f);
    wmma::fill_fragment(acc1, 0.f);

    for (int k0 = 0; k0 < 1024; k0 += 32) {
        #pragma unroll
        for (int it = 0; it < 2; ++it) {
            int f4  = tid + 256 * it;
            int row = f4 >> 3;          // 64 rows, 8 float4 per row
            int c4  = f4 & 7;
            float4 va = *(const float4*)(A  + (size_t)(m0 + row) * 1024 + k0 + c4 * 4);
            float4 vb = *(const float4*)(Bw + (size_t)(n0 + row) * 1024 + k0 + c4 * 4);
            st4_tf32(sA + row * 36 + c4 * 4, va);
            st4_tf32(sB + row * 36 + c4 * 4, vb);
        }
        __syncthreads();
        #pragma unroll
        for (int kk = 0; kk < 4; ++kk) {
            wmma::fragment<wmma::matrix_a, 16, 16, 8, wmma::precision::tf32, wmma::row_major> a0, a1;
            wmma::fragment<wmma::matrix_b, 16, 16, 8, wmma::precision::tf32, wmma::col_major> bf;
            wmma::load_matrix_sync(a0, sA + (wr * 32) * 36 + kk * 8, 36);
            wmma::load_matrix_sync(a1, sA + (wr * 32 + 16) * 36 + kk * 8, 36);
            wmma::load_matrix_sync(bf, sB + (wc * 16) * 36 + kk * 8, 36);
            wmma::mma_sync(acc0, a0, bf, acc0);
            wmma::mma_sync(acc1, a1, bf, acc1);
        }
        __syncthreads();
    }

    if (mode == 1) {
        float* C = g_Y;
        wmma::store_matrix_sync(C + (size_t)(m0 + wr * 32) * 1024 + n0 + wc * 16, acc0, 1024, wmma::mem_row_major);
        wmma::store_matrix_sync(C + (size_t)(m0 + wr * 32 + 16) * 1024 + n0 + wc * 16, acc1, 1024, wmma::mem_row_major);
    } else {
        float* dst = (z == 0) ? g_Q : (z == 1 ? g_K : g_V);
        int b  = m0 / L_;
        int l0 = m0 % L_;
        int hh = n0 >> 6;           // BN=64 == head width
        float* base = dst + (((size_t)(b * H_ + hh)) * L_ + l0 + wr * 32) * DK + wc * 16;
        wmma::store_matrix_sync(base, acc0, 64, wmma::mem_row_major);
        wmma::store_matrix_sync(base + (size_t)16 * 64, acc1, 64, wmma::mem_row_major);
    }
}

// ---------------- fused windowed attention ----------------
#define TQ       32
#define NKP_MAX  1088
#define SLD      (NKP_MAX + 4)      // 1092
#define QLD      72
#define KLD      72
#define ATTN_SMEM_BYTES ((TQ*QLD + 64*KLD + TQ*SLD) * 4 + TQ * 4)

__global__ __launch_bounds__(256) void attn_kernel(
    const float* __restrict__ mask, float* __restrict__ att, int att_en)
{
    extern __shared__ float sm[];
    float* sQ   = sm;                        // 32 x 72
    float* sK   = sQ + TQ * QLD;             // 64 x 72 (K chunks, then V chunks)
    float* sS   = sK + 64 * KLD;             // 32 x SLD (scores -> probs)
    int*  sFlag = (int*)(sS + TQ * SLD);     // 32 masked-row flags

    const int tid  = threadIdx.x;
    const int lane = tid & 31;
    const int w    = tid >> 5;
    const int bh   = blockIdx.y;             // b*H + h
    const int b    = bh >> 4;
    const int h    = bh & 15;
    const int i0   = blockIdx.x * TQ;

    const float* Qh = g_Q + (size_t)bh * L_ * DK;
    const float* Kh = g_K + (size_t)bh * L_ * DK;
    const float* Vh = g_V + (size_t)bh * L_ * DK;

    const int jstart = max(0, i0 - W2);
    const int jend   = min(L_, i0 + TQ - 1 + W2 + 1);
    const int NK     = jend - jstart;
    const int NKP    = (NK + 63) & ~63;

    // ---- load Q tile (tf32) ----
    #pragma unroll
    for (int it = 0; it < 2; ++it) {
        int f4  = tid + 256 * it;
        int row = f4 >> 4, c4 = f4 & 15;
        float4 v = *(const float4*)(Qh + (size_t)(i0 + row) * DK + c4 * 4);
        st4_tf32(sQ + row * QLD + c4 * 4, v);
    }
    if (tid < TQ) sFlag[tid] = 0;
    __syncthreads();

    // ---- scores S = Q K^T (tf32 mma), chunked by 64 keys ----
    const int tr = w >> 2, tc = w & 3;
    for (int j0 = 0; j0 < NKP; j0 += 64) {
        #pragma unroll
        for (int it = 0; it < 4; ++it) {
            int f4  = tid + 256 * it;
            int row = f4 >> 4, c4 = f4 & 15;
            int gj  = jstart + j0 + row;
            float4 v = make_float4(0.f, 0.f, 0.f, 0.f);
            if (gj < jend) v = *(const float4*)(Kh + (size_t)gj * DK + c4 * 4);
            st4_tf32(sK + row * KLD + c4 * 4, v);
        }
        __syncthreads();
        {
            wmma::fragment<wmma::accumulator, 16, 16, 8, float> acc;
            wmma::fill_fragment(acc, 0.f);
            #pragma unroll
            for (int kk = 0; kk < 8; ++kk) {
                wmma::fragment<wmma::matrix_a, 16, 16, 8, wmma::precision::tf32, wmma::row_major> af;
                wmma::fragment<wmma::matrix_b, 16, 16, 8, wmma::precision::tf32, wmma::col_major> bf;
                wmma::load_matrix_sync(af, sQ + (tr * 16) * QLD + kk * 8, QLD);
                wmma::load_matrix_sync(bf, sK + (tc * 16) * KLD + kk * 8, KLD);
                wmma::mma_sync(acc, af, bf, acc);
            }
            wmma::store_matrix_sync(sS + (tr * 16) * SLD + j0 + tc * 16, acc, SLD, wmma::mem_row_major);
        }
        __syncthreads();
    }

    // ---- softmax (fp32, per-row by warps) ----
    const float scale_s = 0.125f;   // 1/sqrt(64)
    for (int qi = w; qi < TQ; qi += 8) {
        const int i = i0 + qi;
        const float mq = mask[b * L_ + i];
        const int lo = max(0, i - W2) - jstart;
        const int hi = min(L_ - 1, i + W2) - jstart;
        float* row = sS + (size_t)qi * SLD;
        if (mq != 0.f) {
            float mmax = -1e30f;
            for (int jj = lo + lane; jj <= hi; jj += 32) {
                float v = row[jj] * scale_s - g_bias[abs(i - (jstart + jj))];
                row[jj] = v;
                mmax = fmaxf(mmax, v);
            }
            #pragma unroll
            for (int o = 16; o; o >>= 1) mmax = fmaxf(mmax, __shfl_xor_sync(0xffffffffu, mmax, o));
            float ssum = 0.f;
            for (int jj = lo + lane; jj <= hi; jj += 32) {
                float p = __expf(row[jj] - mmax);
                row[jj] = p;
                ssum += p;
            }
            #pragma unroll
            for (int o = 16; o; o >>= 1) ssum += __shfl_xor_sync(0xffffffffu, ssum, o);
            float inv = 1.f / ssum;
            for (int jj = lane; jj < NKP; jj += 32) {
                float pv = (jj >= lo && jj <= hi) ? row[jj] * inv : 0.f;
                row[jj] = pv;
            }
        } else {
            // fully masked query row: softmax(NEG - bias) == softmax(-bias) over full L
            if (lane == 0) sFlag[qi] = 1;
            float mmax = -1e30f;
            for (int j = lane; j < L_; j += 32) mmax = fmaxf(mmax, -g_bias[abs(i - j)]);
            #pragma unroll
            for (int o = 16; o; o >>= 1) mmax = fmaxf(mmax, __shfl_xor_sync(0xffffffffu, mmax, o));
            float ssum = 0.f;
            for (int j = lane; j < L_; j += 32) ssum += __expf(-g_bias[abs(i - j)] - mmax);
            #pragma unroll
            for (int o = 16; o; o >>= 1) ssum += __shfl_xor_sync(0xffffffffu, ssum, o);
            float inv = 1.f / ssum;
            if (att_en) {
                float* ar = att + ((size_t)bh * L_ + i) * L_;
                for (int j = lane; j < L_; j += 32)
                    ar[j] = __expf(-g_bias[abs(i - j)] - mmax) * inv;
            }
            float a0 = 0.f, a1 = 0.f;
            for (int j = 0; j < L_; ++j) {
                float p = __expf(-g_bias[abs(i - j)] - mmax) * inv;
                a0 += p * Vh[(size_t)j * DK + lane];
                a1 += p * Vh[(size_t)j * DK + lane + 32];
            }
            float* orow = g_O + ((size_t)(b * L_ + i)) * DM + h * DK;
            orow[lane]      = a0;
            orow[lane + 32] = a1;
            for (int jj = lane; jj < NKP; jj += 32) row[jj] = 0.f;
        }
    }
    __syncthreads();

    // ---- write attention matrix rows (full 2048, zeros outside window) ----
    if (att_en) {
        for (int qi = 0; qi < TQ; ++qi) {
            if (sFlag[qi]) continue;
            const int i = i0 + qi;
            const int lo_g = max(0, i - W2), hi_g = min(L_ - 1, i + W2);
            float* ar = att + ((size_t)bh * L_ + i) * L_;
            const float* row = sS + (size_t)qi * SLD;
            for (int c4 = tid; c4 < L_ / 4; c4 += 256) {
                int c = c4 * 4;
                float4 v;
                v.x = (c     >= lo_g && c     <= hi_g) ? row[c     - jstart] : 0.f;
                v.y = (c + 1 >= lo_g && c + 1 <= hi_g) ? row[c + 1 - jstart] : 0.f;
                v.z = (c + 2 >= lo_g && c + 2 <= hi_g) ? row[c + 2 - jstart] : 0.f;
                v.w = (c + 3 >= lo_g && c + 3 <= hi_g) ? row[c + 3 - jstart] : 0.f;
                *(float4*)(ar + c) = v;
            }
        }
    }
    __syncthreads();

    // ---- round probs to tf32 in place for PV ----
    for (int qi = 0; qi < TQ; ++qi)
        for (int jj = tid; jj < NKP; jj += 256)
            sS[(size_t)qi * SLD + jj] = wmma::__float_to_tf32(sS[(size_t)qi * SLD + jj]);
    __syncthreads();

    // ---- O = P V (tf32 mma) ----
    wmma::fragment<wmma::accumulator, 16, 16, 8, float> accO;
    wmma::fill_fragment(accO, 0.f);
    for (int j0 = 0; j0 < NKP; j0 += 64) {
        #pragma unroll
        for (int it = 0; it < 4; ++it) {
            int f4  = tid + 256 * it;
            int row = f4 >> 4, c4 = f4 & 15;
            int gj  = jstart + j0 + row;
            float4 v = make_float4(0.f, 0.f, 0.f, 0.f);
            if (gj < jend) v = *(const float4*)(Vh + (size_t)gj * DK + c4 * 4);
            st4_tf32(sK + row * KLD + c4 * 4, v);
        }
        __syncthreads();
        #pragma unroll
        for (int kk = 0; kk < 8; ++kk) {
            wmma::fragment<wmma::matrix_a, 16, 16, 8, wmma::precision::tf32, wmma::row_major> af;
            wmma::fragment<wmma::matrix_b, 16, 16, 8, wmma::precision::tf32, wmma::row_major> bf;
            wmma::load_matrix_sync(af, sS + (tr * 16) * SLD + j0 + kk * 8, SLD);
            wmma::load_matrix_sync(bf, sK + (kk * 8) * KLD + tc * 16, KLD);
            wmma::mma_sync(accO, af, bf, accO);
        }
        __syncthreads();
    }
    // stage O in sQ (free now) and copy out
    wmma::store_matrix_sync(sQ + (tr * 16) * QLD + tc * 16, accO, QLD, wmma::mem_row_major);
    __syncthreads();
    for (int t = tid; t < TQ * DK; t += 256) {
        int row = t >> 6, d = t & 63;
        if (!sFlag[row])
            g_O[((size_t)(b * L_ + i0 + row)) * DM + h * DK + d] = sQ[row * QLD + d];
    }
}

// ---------------- residual + LayerNorm ----------------
__global__ __launch_bounds__(256) void ln_kernel(
    const float* __restrict__ q, const float* __restrict__ lnw,
    const float* __restrict__ lnb, float* __restrict__ out)
{
    const int r = blockIdx.x;
    const int tid = threadIdx.x;
    const float* y  = g_Y + (size_t)r * DM;
    const float* qr = q   + (size_t)r * DM;

    float xv[4];
    float s = 0.f, s2 = 0.f;
    #pragma unroll
    for (int it = 0; it < 4; ++it) {
        float v = y[tid + it * 256] + qr[tid + it * 256];
        xv[it] = v; s += v; s2 += v * v;
    }
    #pragma unroll
    for (int o = 16; o; o >>= 1) {
        s  += __shfl_xor_sync(0xffffffffu, s,  o);
        s2 += __shfl_xor_sync(0xffffffffu, s2, o);
    }
    __shared__ float rs[8], rs2[8];
    const int w = tid >> 5, lane = tid & 31;
    if (lane == 0) { rs[w] = s; rs2[w] = s2; }
    __syncthreads();
    if (tid == 0) {
        float a = 0.f, bb = 0.f;
        #pragma unroll
        for (int i = 0; i < 8; ++i) { a += rs[i]; bb += rs2[i]; }
        rs[0] = a; rs2[0] = bb;
    }
    __syncthreads();
    const float mean = rs[0] * (1.f / DM);
    const float var  = rs2[0] * (1.f / DM) - mean * mean;
    const float rstd = rsqrtf(var + 1e-6f);
    #pragma unroll
    for (int it = 0; it < 4; ++it) {
        int d = tid + it * 256;
        out[(size_t)r * DM + d] = (xv[it] - mean) * rstd * lnw[d] + lnb[d];
    }
}

// ---------------- launch ----------------
extern "C" void kernel_launch(void* const* d_in, const int* in_sizes, int n_in,
                              void* d_out, int out_size)
{
    const float* q    = (const float*)d_in[0];
    const float* k    = (const float*)d_in[1];
    const float* v    = (const float*)d_in[2];
    const float* mask = (const float*)d_in[3];
    const float* Wq   = (const float*)d_in[4];
    const float* Wk   = (const float*)d_in[5];
    const float* Wv   = (const float*)d_in[6];
    const float* Wo   = (const float*)d_in[7];
    const float* sf   = (const float*)d_in[8];
    const float* tau  = (const float*)d_in[9];
    const float* lnw  = (const float*)d_in[10];
    const float* lnb  = (const float*)d_in[11];

    float* out = (float*)d_out;
    const long long X_SIZE   = (long long)B_ * L_ * DM;                 // 4,194,304
    const long long ATT_SIZE = (long long)B_ * H_ * L_ * L_;            // 134,217,728
    const int att_en = ((long long)out_size >= X_SIZE + ATT_SIZE) ? 1 : 0;
    float* att = att_en ? (out + X_SIZE) : out;

    cudaFuncSetAttribute(attn_kernel, cudaFuncAttributeMaxDynamicSharedMemorySize, ATTN_SMEM_BYTES);

    // 1) bias table
    bias_kernel<<<(L_ + 255) / 256, 256>>>(sf, tau);
    // 2) Q/K/V projections (one grid, z selects matrix)
    gemm_kernel<<<dim3(DM / 64, (B_ * L_) / 64, 3), 256>>>(q, k, v, Wq, Wk, Wv, 0);
    // 3) fused windowed attention (+ attention-matrix output)
    attn_kernel<<<dim3(L_ / TQ, B_ * H_), 256, ATTN_SMEM_BYTES>>>(mask, att, att_en);
    // 4) output projection
    gemm_kernel<<<dim3(DM / 64, (B_ * L_) / 64, 1), 256>>>(nullptr, nullptr, nullptr, Wo, nullptr, nullptr, 1);
    // 5) residual + LayerNorm -> x
    ln_kernel<<<B_ * L_, 256>>>(q, lnw, lnb, out);
}

// round 5
// speedup vs baseline: 1.3162x; 1.3162x over previous
#include <cuda_runtime.h>
#include <cuda_bf16.h>
#include <mma.h>

using namespace nvcuda;

// ---------------- problem constants (fixed by setup_inputs) ----------------
#define B_   2
#define L_   2048
#define DM   1024
#define H_   16
#define DK   64
#define W2   512          // window_size / 2

// ---------------- device scratch (allocation-free) ----------------
__device__ float g_Q[(size_t)B_ * H_ * L_ * DK];   // [b][h][l][k]  (tf32-rounded)
__device__ float g_K[(size_t)B_ * H_ * L_ * DK];   // (tf32-rounded)
__device__ float g_V[(size_t)B_ * H_ * L_ * DK];   // (tf32-rounded)
__device__ float g_O[(size_t)B_ * L_ * DM];        // [(b*L+l)][h*64+d]
__device__ float g_Y[(size_t)B_ * L_ * DM];        // Wo output
__device__ float g_bias[L_];                       // exp(-|rel|/s/tau), rel=0..L-1

// ---------------- helpers ----------------
__device__ __forceinline__ void st4_tf32(float* d, float4 v) {
    d[0] = wmma::__float_to_tf32(v.x);
    d[1] = wmma::__float_to_tf32(v.y);
    d[2] = wmma::__float_to_tf32(v.z);
    d[3] = wmma::__float_to_tf32(v.w);
}

__device__ __forceinline__ void cp_async16(float* smem_dst, const float* gsrc, int src_bytes) {
    unsigned saddr = (unsigned)__cvta_generic_to_shared(smem_dst);
    asm volatile("cp.async.cg.shared.global [%0], [%1], 16, %2;\n"
                 :: "r"(saddr), "l"(gsrc), "r"(src_bytes));
}
#define CP_COMMIT() asm volatile("cp.async.commit_group;\n" ::: "memory")
#define CP_WAIT(n)  asm volatile("cp.async.wait_group %0;\n" :: "n"(n) : "memory")

// ---------------- bias table ----------------
__global__ void bias_kernel(const float* __restrict__ sf, const float* __restrict__ tau) {
    int r = blockIdx.x * blockDim.x + threadIdx.x;
    if (r < L_) g_bias[r] = expf(-fabsf((float)r / sf[0]) / tau[0]);
}

// ---------------- tf32 GEMM: C[M,N] = A[M,1024] * B[N,1024]^T ----------------
// mode 0: blockIdx.z in {0,1,2} selects (A,B) from q/k/v + Wq/Wk/Wv,
//         writes tf32-ROUNDED head-major g_Q/g_K/g_V
// mode 1: A = g_O, B = B0 (Wo), writes g_Y row-major (full fp32)
__global__ __launch_bounds__(256) void gemm_kernel(
    const float* __restrict__ A0, const float* __restrict__ A1, const float* __restrict__ A2,
    const float* __restrict__ B0, const float* __restrict__ B1, const float* __restrict__ B2,
    int mode)
{
    __shared__ float sA[64 * 36];
    __shared__ float sB[64 * 36];

    const int tid = threadIdx.x;
    const int w   = tid >> 5;
    const int wr  = w >> 2;     // 0..1  (32-row half)
    const int wc  = w & 3;      // 0..3  (16-col slice)
    const int z   = blockIdx.z;
    const int m0  = blockIdx.y * 64;
    const int n0  = blockIdx.x * 64;

    const float* A  = (mode == 1) ? A0 : (z == 0 ? A0 : (z == 1 ? A1 : A2));
    const float* Bw = (mode == 1) ? B0 : (z == 0 ? B0 : (z == 1 ? B1 : B2));
    if (mode == 1) A = g_O;

    wmma::fragment<wmma::accumulator, 16, 16, 8, float> acc0, acc1;
    wmma::fill_fragment(acc0, 0.f);
    wmma::fill_fragment(acc1, 0.f);

    for (int k0 = 0; k0 < 1024; k0 += 32) {
        #pragma unroll
        for (int it = 0; it < 2; ++it) {
            int f4  = tid + 256 * it;
            int row = f4 >> 3;
            int c4  = f4 & 7;
            float4 va = *(const float4*)(A  + (size_t)(m0 + row) * 1024 + k0 + c4 * 4);
            float4 vb = *(const float4*)(Bw + (size_t)(n0 + row) * 1024 + k0 + c4 * 4);
            st4_tf32(sA + row * 36 + c4 * 4, va);
            st4_tf32(sB + row * 36 + c4 * 4, vb);
        }
        __syncthreads();
        #pragma unroll
        for (int kk = 0; kk < 4; ++kk) {
            wmma::fragment<wmma::matrix_a, 16, 16, 8, wmma::precision::tf32, wmma::row_major> a0, a1;
            wmma::fragment<wmma::matrix_b, 16, 16, 8, wmma::precision::tf32, wmma::col_major> bf;
            wmma::load_matrix_sync(a0, sA + (wr * 32) * 36 + kk * 8, 36);
            wmma::load_matrix_sync(a1, sA + (wr * 32 + 16) * 36 + kk * 8, 36);
            wmma::load_matrix_sync(bf, sB + (wc * 16) * 36 + kk * 8, 36);
            wmma::mma_sync(acc0, a0, bf, acc0);
            wmma::mma_sync(acc1, a1, bf, acc1);
        }
        __syncthreads();
    }

    if (mode == 1) {
        float* C = g_Y;
        wmma::store_matrix_sync(C + (size_t)(m0 + wr * 32) * 1024 + n0 + wc * 16, acc0, 1024, wmma::mem_row_major);
        wmma::store_matrix_sync(C + (size_t)(m0 + wr * 32 + 16) * 1024 + n0 + wc * 16, acc1, 1024, wmma::mem_row_major);
    } else {
        // round to tf32 (RN) so attention can use raw copies / raw fragments
        #pragma unroll
        for (int i = 0; i < acc0.num_elements; ++i) {
            acc0.x[i] = wmma::__float_to_tf32(acc0.x[i]);
            acc1.x[i] = wmma::__float_to_tf32(acc1.x[i]);
        }
        float* dst = (z == 0) ? g_Q : (z == 1 ? g_K : g_V);
        int b  = m0 / L_;
        int l0 = m0 % L_;
        int hh = n0 >> 6;
        float* base = dst + (((size_t)(b * H_ + hh)) * L_ + l0 + wr * 32) * DK + wc * 16;
        wmma::store_matrix_sync(base, acc0, 64, wmma::mem_row_major);
        wmma::store_matrix_sync(base + (size_t)16 * 64, acc1, 64, wmma::mem_row_major);
    }
}

// ---------------- fused windowed attention (v2: 512 thr, cp.async pipeline) ----
#define TQ       32
#define CHUNK    128
#define NKP_MAX  1152               // roundup128(1056)
#define SLD      (NKP_MAX + 4)      // 1156
#define KLD      68
#define ATTN_SMEM_BYTES ((TQ * SLD + 2 * CHUNK * KLD) * 4 + 128)

// async-copy one CHUNKx64 tile (rows rbase..rbase+127 of a window with NK valid
// rows) into buf (KLD-strided), zero-filling rows >= NK.
__device__ __forceinline__ void load_chunk_async(float* buf, const float* src,
                                                 int rbase, int NK, int tid) {
    #pragma unroll
    for (int it = 0; it < 4; ++it) {
        int idx = tid + 512 * it;
        int row = idx >> 4, c4 = idx & 15;
        int r   = rbase + row;
        int rc  = min(r, NK - 1);
        cp_async16(buf + row * KLD + c4 * 4,
                   src + (size_t)rc * DK + c4 * 4,
                   (r < NK) ? 16 : 0);
    }
    CP_COMMIT();
}

__global__ __launch_bounds__(512) void attn_kernel(
    const float* __restrict__ mask, float* __restrict__ att, int att_en)
{
    extern __shared__ float sm[];
    float* sS   = sm;                          // 32 x SLD (scores -> probs)
    float* sK   = sS + TQ * SLD;               // 2 x CHUNK x KLD (K, then V, then O staging)
    int*  sFlag = (int*)(sK + 2 * CHUNK * KLD);

    const int tid  = threadIdx.x;
    const int lane = tid & 31;
    const int w    = tid >> 5;                 // 0..15
    const int bh   = blockIdx.y;
    const int b    = bh >> 4;
    const int h    = bh & 15;
    const int i0   = blockIdx.x * TQ;

    const float* Qh = g_Q + (size_t)bh * L_ * DK;
    const float* Kh = g_K + (size_t)bh * L_ * DK;
    const float* Vh = g_V + (size_t)bh * L_ * DK;

    const int jstart = max(0, i0 - W2);
    const int jend   = min(L_, i0 + TQ - 1 + W2 + 1);
    const int NK     = jend - jstart;
    const int NC     = (NK + CHUNK - 1) / CHUNK;
    const int NKP    = NC * CHUNK;

    if (tid < TQ) sFlag[tid] = 0;

    // prefetch K chunk 0
    load_chunk_async(sK, Kh + (size_t)jstart * DK, 0, NK, tid);

    // preload loop-invariant Q fragments straight from global (tf32-rounded)
    const int tr = w >> 3, tc = w & 7;          // QK: 2x8 tiles of 16x16 over 32x128
    wmma::fragment<wmma::matrix_a, 16, 16, 8, wmma::precision::tf32, wmma::row_major> aq[8];
    {
        const float* Qg = Qh + (size_t)(i0 + tr * 16) * DK;
        #pragma unroll
        for (int kk = 0; kk < 8; ++kk)
            wmma::load_matrix_sync(aq[kk], Qg + kk * 8, DK);
    }

    // ---- scores S = Q K^T, 128-key chunks, double-buffered ----
    for (int c = 0; c < NC; ++c) {
        if (c + 1 < NC) {
            load_chunk_async(sK + ((c + 1) & 1) * CHUNK * KLD,
                             Kh + (size_t)jstart * DK, (c + 1) * CHUNK, NK, tid);
            CP_WAIT(1);
        } else {
            CP_WAIT(0);
        }
        __syncthreads();
        const float* kb = sK + (c & 1) * CHUNK * KLD;
        wmma::fragment<wmma::accumulator, 16, 16, 8, float> s;
        wmma::fill_fragment(s, 0.f);
        #pragma unroll
        for (int kk = 0; kk < 8; ++kk) {
            wmma::fragment<wmma::matrix_b, 16, 16, 8, wmma::precision::tf32, wmma::col_major> bf;
            wmma::load_matrix_sync(bf, kb + (tc * 16) * KLD + kk * 8, KLD);
            wmma::mma_sync(s, aq[kk], bf, s);
        }
        wmma::store_matrix_sync(sS + (tr * 16) * SLD + c * CHUNK + tc * 16, s, SLD, wmma::mem_row_major);
        __syncthreads();
    }

    // prefetch V chunk 0 now — overlaps softmax + attention-matrix write
    load_chunk_async(sK, Vh + (size_t)jstart * DK, 0, NK, tid);

    // ---- softmax (fp32, 2 rows per warp) ----
    const float scale_s = 0.125f;   // 1/sqrt(64)
    for (int qi = w; qi < TQ; qi += 16) {
        const int i = i0 + qi;
        const float mq = mask[b * L_ + i];
        const int lo = max(0, i - W2) - jstart;
        const int hi = min(L_ - 1, i + W2) - jstart;
        float* row = sS + (size_t)qi * SLD;
        if (mq != 0.f) {
            float mmax = -1e30f;
            for (int jj = lo + lane; jj <= hi; jj += 32) {
                float v = row[jj] * scale_s - g_bias[abs(i - (jstart + jj))];
                row[jj] = v;
                mmax = fmaxf(mmax, v);
            }
            #pragma unroll
            for (int o = 16; o; o >>= 1) mmax = fmaxf(mmax, __shfl_xor_sync(0xffffffffu, mmax, o));
            float ssum = 0.f;
            for (int jj = lo + lane; jj <= hi; jj += 32) {
                float p = __expf(row[jj] - mmax);
                row[jj] = p;
                ssum += p;
            }
            #pragma unroll
            for (int o = 16; o; o >>= 1) ssum += __shfl_xor_sync(0xffffffffu, ssum, o);
            float inv = 1.f / ssum;
            for (int jj = lane; jj < NKP; jj += 32) {
                float pv = (jj >= lo && jj <= hi) ? row[jj] * inv : 0.f;
                row[jj] = pv;
            }
        } else {
            // fully masked query row: softmax(NEG - bias) == softmax(-bias) over full L
            if (lane == 0) sFlag[qi] = 1;
            float mmax = -1e30f;
            for (int j = lane; j < L_; j += 32) mmax = fmaxf(mmax, -g_bias[abs(i - j)]);
            #pragma unroll
            for (int o = 16; o; o >>= 1) mmax = fmaxf(mmax, __shfl_xor_sync(0xffffffffu, mmax, o));
            float ssum = 0.f;
            for (int j = lane; j < L_; j += 32) ssum += __expf(-g_bias[abs(i - j)] - mmax);
            #pragma unroll
            for (int o = 16; o; o >>= 1) ssum += __shfl_xor_sync(0xffffffffu, ssum, o);
            float inv = 1.f / ssum;
            if (att_en) {
                float* ar = att + ((size_t)bh * L_ + i) * L_;
                for (int j = lane; j < L_; j += 32)
                    ar[j] = __expf(-g_bias[abs(i - j)] - mmax) * inv;
            }
            float a0 = 0.f, a1 = 0.f;
            for (int j = 0; j < L_; ++j) {
                float p = __expf(-g_bias[abs(i - j)] - mmax) * inv;
                a0 += p * Vh[(size_t)j * DK + lane];
                a1 += p * Vh[(size_t)j * DK + lane + 32];
            }
            float* orow = g_O + ((size_t)(b * L_ + i)) * DM + h * DK;
            orow[lane]      = a0;
            orow[lane + 32] = a1;
            for (int jj = lane; jj < NKP; jj += 32) row[jj] = 0.f;
        }
    }
    __syncthreads();

    // ---- write attention matrix rows (full 2048, zeros outside window) ----
    if (att_en) {
        for (int t = tid; t < TQ * (L_ / 4); t += 512) {
            int qi = t >> 9;          // L_/4 = 512 float4 per row
            if (sFlag[qi]) continue;
            int c4 = t & 511;
            int i  = i0 + qi;
            int lo_g = max(0, i - W2), hi_g = min(L_ - 1, i + W2);
            int cc = c4 * 4;
            const float* row = sS + (size_t)qi * SLD;
            float4 v;
            v.x = (cc     >= lo_g && cc     <= hi_g) ? row[cc     - jstart] : 0.f;
            v.y = (cc + 1 >= lo_g && cc + 1 <= hi_g) ? row[cc + 1 - jstart] : 0.f;
            v.z = (cc + 2 >= lo_g && cc + 2 <= hi_g) ? row[cc + 2 - jstart] : 0.f;
            v.w = (cc + 3 >= lo_g && cc + 3 <= hi_g) ? row[cc + 3 - jstart] : 0.f;
            *(float4*)(att + ((size_t)bh * L_ + i) * L_ + cc) = v;
        }
    }
    // no barrier needed here: PV's first CP_WAIT + __syncthreads covers it,
    // and PV only reads sS (stable) + the V buffers.

    // ---- O = P V (tf32 mma), chunk split across two 8-warp groups ----
    wmma::fragment<wmma::accumulator, 16, 16, 8, float> accO;
    wmma::fill_fragment(accO, 0.f);
    const int gsel = w >> 3, wl = w & 7, tr2 = wl >> 2, tc2 = wl & 3;
    for (int c = 0; c < NC; ++c) {
        if (c + 1 < NC) {
            load_chunk_async(sK + ((c + 1) & 1) * CHUNK * KLD,
                             Vh + (size_t)jstart * DK, (c + 1) * CHUNK, NK, tid);
            CP_WAIT(1);
        } else {
            CP_WAIT(0);
        }
        __syncthreads();
        const float* vb = sK + (c & 1) * CHUNK * KLD;
        #pragma unroll
        for (int kk = 0; kk < 8; ++kk) {
            wmma::fragment<wmma::matrix_a, 16, 16, 8, wmma::precision::tf32, wmma::row_major> af;
            wmma::fragment<wmma::matrix_b, 16, 16, 8, wmma::precision::tf32, wmma::row_major> bf;
            wmma::load_matrix_sync(af, sS + (tr2 * 16) * SLD + c * CHUNK + gsel * 64 + kk * 8, SLD);
            wmma::load_matrix_sync(bf, vb + (gsel * 64 + kk * 8) * KLD + tc2 * 16, KLD);
            wmma::mma_sync(accO, af, bf, accO);
        }
        __syncthreads();
    }

    // stage both groups' partial O and combine
    float* sO = sK;   // buffers are free now
    wmma::store_matrix_sync(sO + gsel * (TQ * KLD) + (tr2 * 16) * KLD + tc2 * 16,
                            accO, KLD, wmma::mem_row_major);
    __syncthreads();
    for (int t = tid; t < TQ * DK; t += 512) {
        int row = t >> 6, d = t & 63;
        if (!sFlag[row])
            g_O[((size_t)(b * L_ + i0 + row)) * DM + h * DK + d] =
                sO[row * KLD + d] + sO[TQ * KLD + row * KLD + d];
    }
}

// ---------------- residual + LayerNorm ----------------
__global__ __launch_bounds__(256) void ln_kernel(
    const float* __restrict__ q, const float* __restrict__ lnw,
    const float* __restrict__ lnb, float* __restrict__ out)
{
    const int r = blockIdx.x;
    const int tid = threadIdx.x;
    const float* y  = g_Y + (size_t)r * DM;
    const float* qr = q   + (size_t)r * DM;

    float xv[4];
    float s = 0.f, s2 = 0.f;
    #pragma unroll
    for (int it = 0; it < 4; ++it) {
        float v = y[tid + it * 256] + qr[tid + it * 256];
        xv[it] = v; s += v; s2 += v * v;
    }
    #pragma unroll
    for (int o = 16; o; o >>= 1) {
        s  += __shfl_xor_sync(0xffffffffu, s,  o);
        s2 += __shfl_xor_sync(0xffffffffu, s2, o);
    }
    __shared__ float rs[8], rs2[8];
    const int w = tid >> 5, lane = tid & 31;
    if (lane == 0) { rs[w] = s; rs2[w] = s2; }
    __syncthreads();
    if (tid == 0) {
        float a = 0.f, bb = 0.f;
        #pragma unroll
        for (int i = 0; i < 8; ++i) { a += rs[i]; bb += rs2[i]; }
        rs[0] = a; rs2[0] = bb;
    }
    __syncthreads();
    const float mean = rs[0] * (1.f / DM);
    const float var  = rs2[0] * (1.f / DM) - mean * mean;
    const float rstd = rsqrtf(var + 1e-6f);
    #pragma unroll
    for (int it = 0; it < 4; ++it) {
        int d = tid + it * 256;
        out[(size_t)r * DM + d] = (xv[it] - mean) * rstd * lnw[d] + lnb[d];
    }
}

// ---------------- launch ----------------
extern "C" void kernel_launch(void* const* d_in, const int* in_sizes, int n_in,
                              void* d_out, int out_size)
{
    const float* q    = (const float*)d_in[0];
    const float* k    = (const float*)d_in[1];
    const float* v    = (const float*)d_in[2];
    const float* mask = (const float*)d_in[3];
    const float* Wq   = (const float*)d_in[4];
    const float* Wk   = (const float*)d_in[5];
    const float* Wv   = (const float*)d_in[6];
    const float* Wo   = (const float*)d_in[7];
    const float* sf   = (const float*)d_in[8];
    const float* tau  = (const float*)d_in[9];
    const float* lnw  = (const float*)d_in[10];
    const float* lnb  = (const float*)d_in[11];

    float* out = (float*)d_out;
    const long long X_SIZE   = (long long)B_ * L_ * DM;                 // 4,194,304
    const long long ATT_SIZE = (long long)B_ * H_ * L_ * L_;            // 134,217,728
    const int att_en = ((long long)out_size >= X_SIZE + ATT_SIZE) ? 1 : 0;
    float* att = att_en ? (out + X_SIZE) : out;

    cudaFuncSetAttribute(attn_kernel, cudaFuncAttributeMaxDynamicSharedMemorySize, ATTN_SMEM_BYTES);

    // 1) bias table
    bias_kernel<<<(L_ + 255) / 256, 256>>>(sf, tau);
    // 2) Q/K/V projections (one grid, z selects matrix), tf32-rounded outputs
    gemm_kernel<<<dim3(DM / 64, (B_ * L_) / 64, 3), 256>>>(q, k, v, Wq, Wk, Wv, 0);
    // 3) fused windowed attention (+ attention-matrix output)
    attn_kernel<<<dim3(L_ / TQ, B_ * H_), 512, ATTN_SMEM_BYTES>>>(mask, att, att_en);
    // 4) output projection
    gemm_kernel<<<dim3(DM / 64, (B_ * L_) / 64, 1), 256>>>(nullptr, nullptr, nullptr, Wo, nullptr, nullptr, 1);
    // 5) residual + LayerNorm -> x
    ln_kernel<<<B_ * L_, 256>>>(q, lnw, lnb, out);
}

// round 6
// speedup vs baseline: 1.4309x; 1.0871x over previous
#include <cuda_runtime.h>
#include <cuda_bf16.h>
#include <mma.h>

using namespace nvcuda;

// ---------------- problem constants (fixed by setup_inputs) ----------------
#define B_   2
#define L_   2048
#define DM   1024
#define H_   16
#define DK   64
#define W2   512          // window_size / 2

// ---------------- device scratch (allocation-free) ----------------
__device__ float g_Q[(size_t)B_ * H_ * L_ * DK];   // [b][h][l][k]  (tf32-rounded)
__device__ float g_K[(size_t)B_ * H_ * L_ * DK];   // (tf32-rounded)
__device__ float g_V[(size_t)B_ * H_ * L_ * DK];   // (tf32-rounded)
__device__ float g_O[(size_t)B_ * L_ * DM];        // [(b*L+l)][h*64+d]
__device__ float g_Y[(size_t)B_ * L_ * DM];        // Wo output
__device__ float g_bias[L_];                       // exp(-|rel|/s/tau), rel=0..L-1

// ---------------- helpers ----------------
__device__ __forceinline__ void cp_async16(float* smem_dst, const float* gsrc, int src_bytes) {
    unsigned saddr = (unsigned)__cvta_generic_to_shared(smem_dst);
    asm volatile("cp.async.cg.shared.global [%0], [%1], 16, %2;\n"
                 :: "r"(saddr), "l"(gsrc), "r"(src_bytes));
}
#define CP_COMMIT() asm volatile("cp.async.commit_group;\n" ::: "memory")
#define CP_WAIT(n)  asm volatile("cp.async.wait_group %0;\n" :: "n"(n) : "memory")

// ---------------- bias table ----------------
__global__ void bias_kernel(const float* __restrict__ sf, const float* __restrict__ tau) {
    int r = blockIdx.x * blockDim.x + threadIdx.x;
    if (r < L_) g_bias[r] = expf(-fabsf((float)r / sf[0]) / tau[0]);
}

// ---------------- tf32 GEMM v2: C[M,N] = A[M,1024] * B[N,1024]^T ------------
// 128x128 CTA tile, 256 thr, warp tile 64x32 (4x2 accs), cp.async dbl-buffer.
// mode 0: z in {0,1,2} selects q/k/v x Wq/Wk/Wv -> tf32-rounded head-major Q/K/V
// mode 1: A = g_O, B = B0 (Wo) -> g_Y row-major
#define GBM 128
#define GBN 128
#define GBK 32
#define GLD 36

__global__ __launch_bounds__(256, 2) void gemm_kernel(
    const float* __restrict__ A0, const float* __restrict__ A1, const float* __restrict__ A2,
    const float* __restrict__ B0, const float* __restrict__ B1, const float* __restrict__ B2,
    int mode)
{
    __shared__ float sA[2][GBM * GLD];
    __shared__ float sB[2][GBN * GLD];

    const int tid = threadIdx.x;
    const int w   = tid >> 5;
    const int wr  = w >> 2;     // 0..1  -> 64-row half
    const int wc  = w & 3;      // 0..3  -> 32-col slice
    const int z   = blockIdx.z;
    const int m0  = blockIdx.y * GBM;
    const int n0  = blockIdx.x * GBN;

    const float* A  = (mode == 1) ? g_O : (z == 0 ? A0 : (z == 1 ? A1 : A2));
    const float* Bw = (mode == 1) ? B0  : (z == 0 ? B0 : (z == 1 ? B1 : B2));

    wmma::fragment<wmma::accumulator, 16, 16, 8, float> acc[4][2];
    #pragma unroll
    for (int ri = 0; ri < 4; ++ri)
        #pragma unroll
        for (int ci = 0; ci < 2; ++ci)
            wmma::fill_fragment(acc[ri][ci], 0.f);

    // ---- async tile loader: 128x32 of A and of B (8 cp.async/thread) ----
    #define LOAD_TILE(buf, k0)                                                   \
        do {                                                                     \
            _Pragma("unroll")                                                    \
            for (int it = 0; it < 4; ++it) {                                     \
                int idx = tid + it * 256;                                        \
                int row = idx >> 3, c4 = idx & 7;                                \
                cp_async16(&sA[buf][row * GLD + c4 * 4],                         \
                           A  + (size_t)(m0 + row) * 1024 + (k0) + c4 * 4, 16);  \
                cp_async16(&sB[buf][row * GLD + c4 * 4],                         \
                           Bw + (size_t)(n0 + row) * 1024 + (k0) + c4 * 4, 16);  \
            }                                                                    \
            CP_COMMIT();                                                         \
        } while (0)

    LOAD_TILE(0, 0);

    for (int c = 0; c < 1024 / GBK; ++c) {
        if (c + 1 < 1024 / GBK) {
            LOAD_TILE((c + 1) & 1, (c + 1) * GBK);
            CP_WAIT(1);
        } else {
            CP_WAIT(0);
        }
        __syncthreads();
        const float* a_ = sA[c & 1];
        const float* b_ = sB[c & 1];
        #pragma unroll
        for (int kk = 0; kk < 4; ++kk) {
            wmma::fragment<wmma::matrix_a, 16, 16, 8, wmma::precision::tf32, wmma::row_major> af[4];
            wmma::fragment<wmma::matrix_b, 16, 16, 8, wmma::precision::tf32, wmma::col_major> bf[2];
            #pragma unroll
            for (int ri = 0; ri < 4; ++ri)
                wmma::load_matrix_sync(af[ri], a_ + (wr * 64 + ri * 16) * GLD + kk * 8, GLD);
            #pragma unroll
            for (int ci = 0; ci < 2; ++ci)
                wmma::load_matrix_sync(bf[ci], b_ + (wc * 32 + ci * 16) * GLD + kk * 8, GLD);
            #pragma unroll
            for (int ri = 0; ri < 4; ++ri)
                #pragma unroll
                for (int ci = 0; ci < 2; ++ci)
                    wmma::mma_sync(acc[ri][ci], af[ri], bf[ci], acc[ri][ci]);
        }
        __syncthreads();
    }
    #undef LOAD_TILE

    if (mode == 1) {
        #pragma unroll
        for (int ri = 0; ri < 4; ++ri)
            #pragma unroll
            for (int ci = 0; ci < 2; ++ci)
                wmma::store_matrix_sync(
                    g_Y + (size_t)(m0 + wr * 64 + ri * 16) * 1024 + n0 + wc * 32 + ci * 16,
                    acc[ri][ci], 1024, wmma::mem_row_major);
    } else {
        // RN-round to tf32 so attention can use raw fragments of Q/K/V
        #pragma unroll
        for (int ri = 0; ri < 4; ++ri)
            #pragma unroll
            for (int ci = 0; ci < 2; ++ci)
                #pragma unroll
                for (int i = 0; i < acc[ri][ci].num_elements; ++i)
                    acc[ri][ci].x[i] = wmma::__float_to_tf32(acc[ri][ci].x[i]);
        float* dst = (z == 0) ? g_Q : (z == 1 ? g_K : g_V);
        const int b  = m0 / L_;
        const int l0 = m0 % L_;
        const int hh = (n0 + wc * 32) >> 6;        // head index
        const int hc = (wc * 32) & 63;             // within-head col offset
        #pragma unroll
        for (int ri = 0; ri < 4; ++ri)
            #pragma unroll
            for (int ci = 0; ci < 2; ++ci)
                wmma::store_matrix_sync(
                    dst + (((size_t)(b * H_ + hh)) * L_ + l0 + wr * 64 + ri * 16) * DK + hc + ci * 16,
                    acc[ri][ci], DK, wmma::mem_row_major);
    }
}

// ---------------- fused windowed attention (512 thr, cp.async pipeline) ------
#define TQ       32
#define CHUNK    128
#define NKP_MAX  1152               // roundup128(1056)
#define SLD      (NKP_MAX + 4)      // 1156
#define KLD      68
#define ATTN_SMEM_BYTES ((TQ * SLD + 2 * CHUNK * KLD) * 4 + 128)

__device__ __forceinline__ void load_chunk_async(float* buf, const float* src,
                                                 int rbase, int NK, int tid) {
    #pragma unroll
    for (int it = 0; it < 4; ++it) {
        int idx = tid + 512 * it;
        int row = idx >> 4, c4 = idx & 15;
        int r   = rbase + row;
        int rc  = min(r, NK - 1);
        cp_async16(buf + row * KLD + c4 * 4,
                   src + (size_t)rc * DK + c4 * 4,
                   (r < NK) ? 16 : 0);
    }
    CP_COMMIT();
}

__global__ __launch_bounds__(512) void attn_kernel(
    const float* __restrict__ mask, float* __restrict__ att, int att_en)
{
    extern __shared__ float sm[];
    float* sS   = sm;                          // 32 x SLD (scores -> probs)
    float* sK   = sS + TQ * SLD;               // 2 x CHUNK x KLD
    int*  sFlag = (int*)(sK + 2 * CHUNK * KLD);

    const int tid  = threadIdx.x;
    const int lane = tid & 31;
    const int w    = tid >> 5;
    const int bh   = blockIdx.y;
    const int b    = bh >> 4;
    const int h    = bh & 15;
    const int i0   = blockIdx.x * TQ;

    const float* Qh = g_Q + (size_t)bh * L_ * DK;
    const float* Kh = g_K + (size_t)bh * L_ * DK;
    const float* Vh = g_V + (size_t)bh * L_ * DK;

    const int jstart = max(0, i0 - W2);
    const int jend   = min(L_, i0 + TQ - 1 + W2 + 1);
    const int NK     = jend - jstart;
    const int NC     = (NK + CHUNK - 1) / CHUNK;
    const int NKP    = NC * CHUNK;

    if (tid < TQ) sFlag[tid] = 0;

    load_chunk_async(sK, Kh + (size_t)jstart * DK, 0, NK, tid);

    const int tr = w >> 3, tc = w & 7;
    wmma::fragment<wmma::matrix_a, 16, 16, 8, wmma::precision::tf32, wmma::row_major> aq[8];
    {
        const float* Qg = Qh + (size_t)(i0 + tr * 16) * DK;
        #pragma unroll
        for (int kk = 0; kk < 8; ++kk)
            wmma::load_matrix_sync(aq[kk], Qg + kk * 8, DK);
    }

    // ---- scores S = Q K^T, 128-key chunks, double-buffered ----
    for (int c = 0; c < NC; ++c) {
        if (c + 1 < NC) {
            load_chunk_async(sK + ((c + 1) & 1) * CHUNK * KLD,
                             Kh + (size_t)jstart * DK, (c + 1) * CHUNK, NK, tid);
            CP_WAIT(1);
        } else {
            CP_WAIT(0);
        }
        __syncthreads();
        const float* kb = sK + (c & 1) * CHUNK * KLD;
        wmma::fragment<wmma::accumulator, 16, 16, 8, float> s;
        wmma::fill_fragment(s, 0.f);
        #pragma unroll
        for (int kk = 0; kk < 8; ++kk) {
            wmma::fragment<wmma::matrix_b, 16, 16, 8, wmma::precision::tf32, wmma::col_major> bf;
            wmma::load_matrix_sync(bf, kb + (tc * 16) * KLD + kk * 8, KLD);
            wmma::mma_sync(s, aq[kk], bf, s);
        }
        wmma::store_matrix_sync(sS + (tr * 16) * SLD + c * CHUNK + tc * 16, s, SLD, wmma::mem_row_major);
        __syncthreads();
    }

    // prefetch V chunk 0 — overlaps softmax + att-matrix write
    load_chunk_async(sK, Vh + (size_t)jstart * DK, 0, NK, tid);

    // ---- softmax (fp32, 2 rows per warp) ----
    const float scale_s = 0.125f;
    for (int qi = w; qi < TQ; qi += 16) {
        const int i = i0 + qi;
        const float mq = mask[b * L_ + i];
        const int lo = max(0, i - W2) - jstart;
        const int hi = min(L_ - 1, i + W2) - jstart;
        float* row = sS + (size_t)qi * SLD;
        if (mq != 0.f) {
            float mmax = -1e30f;
            for (int jj = lo + lane; jj <= hi; jj += 32) {
                float v = row[jj] * scale_s - g_bias[abs(i - (jstart + jj))];
                row[jj] = v;
                mmax = fmaxf(mmax, v);
            }
            #pragma unroll
            for (int o = 16; o; o >>= 1) mmax = fmaxf(mmax, __shfl_xor_sync(0xffffffffu, mmax, o));
            float ssum = 0.f;
            for (int jj = lo + lane; jj <= hi; jj += 32) {
                float p = __expf(row[jj] - mmax);
                row[jj] = p;
                ssum += p;
            }
            #pragma unroll
            for (int o = 16; o; o >>= 1) ssum += __shfl_xor_sync(0xffffffffu, ssum, o);
            float inv = 1.f / ssum;
            for (int jj = lane; jj < NKP; jj += 32) {
                float pv = (jj >= lo && jj <= hi) ? row[jj] * inv : 0.f;
                row[jj] = pv;
            }
        } else {
            if (lane == 0) sFlag[qi] = 1;
            float mmax = -1e30f;
            for (int j = lane; j < L_; j += 32) mmax = fmaxf(mmax, -g_bias[abs(i - j)]);
            #pragma unroll
            for (int o = 16; o; o >>= 1) mmax = fmaxf(mmax, __shfl_xor_sync(0xffffffffu, mmax, o));
            float ssum = 0.f;
            for (int j = lane; j < L_; j += 32) ssum += __expf(-g_bias[abs(i - j)] - mmax);
            #pragma unroll
            for (int o = 16; o; o >>= 1) ssum += __shfl_xor_sync(0xffffffffu, ssum, o);
            float inv = 1.f / ssum;
            if (att_en) {
                float* ar = att + ((size_t)bh * L_ + i) * L_;
                for (int j = lane; j < L_; j += 32)
                    ar[j] = __expf(-g_bias[abs(i - j)] - mmax) * inv;
            }
            float a0 = 0.f, a1 = 0.f;
            for (int j = 0; j < L_; ++j) {
                float p = __expf(-g_bias[abs(i - j)] - mmax) * inv;
                a0 += p * Vh[(size_t)j * DK + lane];
                a1 += p * Vh[(size_t)j * DK + lane + 32];
            }
            float* orow = g_O + ((size_t)(b * L_ + i)) * DM + h * DK;
            orow[lane]      = a0;
            orow[lane + 32] = a1;
            for (int jj = lane; jj < NKP; jj += 32) row[jj] = 0.f;
        }
    }
    __syncthreads();

    // ---- write attention matrix rows (full 2048, zeros outside window) ----
    if (att_en) {
        for (int t = tid; t < TQ * (L_ / 4); t += 512) {
            int qi = t >> 9;
            if (sFlag[qi]) continue;
            int c4 = t & 511;
            int i  = i0 + qi;
            int lo_g = max(0, i - W2), hi_g = min(L_ - 1, i + W2);
            int cc = c4 * 4;
            const float* row = sS + (size_t)qi * SLD;
            float4 v;
            v.x = (cc     >= lo_g && cc     <= hi_g) ? row[cc     - jstart] : 0.f;
            v.y = (cc + 1 >= lo_g && cc + 1 <= hi_g) ? row[cc + 1 - jstart] : 0.f;
            v.z = (cc + 2 >= lo_g && cc + 2 <= hi_g) ? row[cc + 2 - jstart] : 0.f;
            v.w = (cc + 3 >= lo_g && cc + 3 <= hi_g) ? row[cc + 3 - jstart] : 0.f;
            *(float4*)(att + ((size_t)bh * L_ + i) * L_ + cc) = v;
        }
    }

    // ---- O = P V (tf32 mma), chunk split across two 8-warp groups ----
    wmma::fragment<wmma::accumulator, 16, 16, 8, float> accO;
    wmma::fill_fragment(accO, 0.f);
    const int gsel = w >> 3, wl = w & 7, tr2 = wl >> 2, tc2 = wl & 3;
    for (int c = 0; c < NC; ++c) {
        if (c + 1 < NC) {
            load_chunk_async(sK + ((c + 1) & 1) * CHUNK * KLD,
                             Vh + (size_t)jstart * DK, (c + 1) * CHUNK, NK, tid);
            CP_WAIT(1);
        } else {
            CP_WAIT(0);
        }
        __syncthreads();
        const float* vb = sK + (c & 1) * CHUNK * KLD;
        #pragma unroll
        for (int kk = 0; kk < 8; ++kk) {
            wmma::fragment<wmma::matrix_a, 16, 16, 8, wmma::precision::tf32, wmma::row_major> af;
            wmma::fragment<wmma::matrix_b, 16, 16, 8, wmma::precision::tf32, wmma::row_major> bf;
            wmma::load_matrix_sync(af, sS + (tr2 * 16) * SLD + c * CHUNK + gsel * 64 + kk * 8, SLD);
            wmma::load_matrix_sync(bf, vb + (gsel * 64 + kk * 8) * KLD + tc2 * 16, KLD);
            wmma::mma_sync(accO, af, bf, accO);
        }
        __syncthreads();
    }

    float* sO = sK;
    wmma::store_matrix_sync(sO + gsel * (TQ * KLD) + (tr2 * 16) * KLD + tc2 * 16,
                            accO, KLD, wmma::mem_row_major);
    __syncthreads();
    for (int t = tid; t < TQ * DK; t += 512) {
        int row = t >> 6, d = t & 63;
        if (!sFlag[row])
            g_O[((size_t)(b * L_ + i0 + row)) * DM + h * DK + d] =
                sO[row * KLD + d] + sO[TQ * KLD + row * KLD + d];
    }
}

// ---------------- residual + LayerNorm ----------------
__global__ __launch_bounds__(256) void ln_kernel(
    const float* __restrict__ q, const float* __restrict__ lnw,
    const float* __restrict__ lnb, float* __restrict__ out)
{
    const int r = blockIdx.x;
    const int tid = threadIdx.x;
    const float* y  = g_Y + (size_t)r * DM;
    const float* qr = q   + (size_t)r * DM;

    float xv[4];
    float s = 0.f, s2 = 0.f;
    #pragma unroll
    for (int it = 0; it < 4; ++it) {
        float v = y[tid + it * 256] + qr[tid + it * 256];
        xv[it] = v; s += v; s2 += v * v;
    }
    #pragma unroll
    for (int o = 16; o; o >>= 1) {
        s  += __shfl_xor_sync(0xffffffffu, s,  o);
        s2 += __shfl_xor_sync(0xffffffffu, s2, o);
    }
    __shared__ float rs[8], rs2[8];
    const int w = tid >> 5, lane = tid & 31;
    if (lane == 0) { rs[w] = s; rs2[w] = s2; }
    __syncthreads();
    if (tid == 0) {
        float a = 0.f, bb = 0.f;
        #pragma unroll
        for (int i = 0; i < 8; ++i) { a += rs[i]; bb += rs2[i]; }
        rs[0] = a; rs2[0] = bb;
    }
    __syncthreads();
    const float mean = rs[0] * (1.f / DM);
    const float var  = rs2[0] * (1.f / DM) - mean * mean;
    const float rstd = rsqrtf(var + 1e-6f);
    #pragma unroll
    for (int it = 0; it < 4; ++it) {
        int d = tid + it * 256;
        out[(size_t)r * DM + d] = (xv[it] - mean) * rstd * lnw[d] + lnb[d];
    }
}

// ---------------- launch ----------------
extern "C" void kernel_launch(void* const* d_in, const int* in_sizes, int n_in,
                              void* d_out, int out_size)
{
    const float* q    = (const float*)d_in[0];
    const float* k    = (const float*)d_in[1];
    const float* v    = (const float*)d_in[2];
    const float* mask = (const float*)d_in[3];
    const float* Wq   = (const float*)d_in[4];
    const float* Wk   = (const float*)d_in[5];
    const float* Wv   = (const float*)d_in[6];
    const float* Wo   = (const float*)d_in[7];
    const float* sf   = (const float*)d_in[8];
    const float* tau  = (const float*)d_in[9];
    const float* lnw  = (const float*)d_in[10];
    const float* lnb  = (const float*)d_in[11];

    float* out = (float*)d_out;
    const long long X_SIZE   = (long long)B_ * L_ * DM;
    const long long ATT_SIZE = (long long)B_ * H_ * L_ * L_;
    const int att_en = ((long long)out_size >= X_SIZE + ATT_SIZE) ? 1 : 0;
    float* att = att_en ? (out + X_SIZE) : out;

    cudaFuncSetAttribute(attn_kernel, cudaFuncAttributeMaxDynamicSharedMemorySize, ATTN_SMEM_BYTES);

    // 1) bias table
    bias_kernel<<<(L_ + 255) / 256, 256>>>(sf, tau);
    // 2) Q/K/V projections (z selects matrix), tf32-rounded outputs
    gemm_kernel<<<dim3(DM / GBN, (B_ * L_) / GBM, 3), 256>>>(q, k, v, Wq, Wk, Wv, 0);
    // 3) fused windowed attention (+ attention-matrix output)
    attn_kernel<<<dim3(L_ / TQ, B_ * H_), 512, ATTN_SMEM_BYTES>>>(mask, att, att_en);
    // 4) output projection
    gemm_kernel<<<dim3(DM / GBN, (B_ * L_) / GBM, 1), 256>>>(nullptr, nullptr, nullptr, Wo, nullptr, nullptr, 1);
    // 5) residual + LayerNorm -> x
    ln_kernel<<<B_ * L_, 256>>>(q, lnw, lnb, out);
}